// round 3
// baseline (speedup 1.0000x reference)
#include <cuda_runtime.h>
#include <cuda_bf16.h>
#include <cstdint>

#define QB 4096
#define ND 8192
#define KD 1024
#define NT_TILES 64       // 8192 / 128
#define INV_TEMP 50.0f    // 1 / 0.02
#define ROWB 80           // smem bytes per 32-bf16 row (64B data + 16B pad, conflict-free LDSM)

// ---------------- device scratch (no allocations allowed) ----------------
__device__ __align__(16) __nv_bfloat16 g_Qb[(size_t)QB * KD];
__device__ __align__(16) __nv_bfloat16 g_Db[(size_t)ND * KD];
__device__ float2 g_part[(size_t)QB * NT_TILES];
__device__ float  g_pos[QB];
__device__ float  g_rowloss[QB];

// ---------------- kernel 1: fp32 -> bf16 convert ----------------
__global__ __launch_bounds__(256) void convert_kernel(const float* __restrict__ q,
                                                      const float* __restrict__ dd) {
    int idx = blockIdx.x * 256 + threadIdx.x;
    const int QN4 = QB * KD / 4;
    const int DN4 = ND * KD / 4;
    if (idx < QN4) {
        float4 f = ((const float4*)q)[idx];
        __nv_bfloat162 h0 = __floats2bfloat162_rn(f.x, f.y);
        __nv_bfloat162 h1 = __floats2bfloat162_rn(f.z, f.w);
        uint2 u;
        u.x = *(uint32_t*)&h0;
        u.y = *(uint32_t*)&h1;
        ((uint2*)g_Qb)[idx] = u;
    } else if (idx < QN4 + DN4) {
        int j = idx - QN4;
        float4 f = ((const float4*)dd)[j];
        __nv_bfloat162 h0 = __floats2bfloat162_rn(f.x, f.y);
        __nv_bfloat162 h1 = __floats2bfloat162_rn(f.z, f.w);
        uint2 u;
        u.x = *(uint32_t*)&h0;
        u.y = *(uint32_t*)&h1;
        ((uint2*)g_Db)[j] = u;
    }
}

// ---------------- mma helpers ----------------
__device__ __forceinline__ void ldsm4(uint32_t addr, uint32_t& r0, uint32_t& r1,
                                      uint32_t& r2, uint32_t& r3) {
    asm volatile("ldmatrix.sync.aligned.m8n8.x4.shared.b16 {%0,%1,%2,%3}, [%4];"
                 : "=r"(r0), "=r"(r1), "=r"(r2), "=r"(r3)
                 : "r"(addr));
}

__device__ __forceinline__ void mma16816(float c[4], const uint32_t a[4], const uint32_t b[2]) {
    asm volatile("mma.sync.aligned.m16n8k16.row.col.f32.bf16.bf16.f32 "
                 "{%0,%1,%2,%3}, {%4,%5,%6,%7}, {%8,%9}, {%0,%1,%2,%3};"
                 : "+f"(c[0]), "+f"(c[1]), "+f"(c[2]), "+f"(c[3])
                 : "r"(a[0]), "r"(a[1]), "r"(a[2]), "r"(a[3]), "r"(b[0]), "r"(b[1]));
}

// ---------------- kernel 2: tiled GEMM + per-tile online LSE partials ----------------
// grid: (NT_TILES=64, 32), 256 threads. CTA computes logits[mt*128:+128, nt*128:+128]
// over full K=1024, then writes per-row (max, sumexp) partials and the positive logit.
__global__ __launch_bounds__(256, 1) void gemm_lse_kernel() {
    const int nt   = blockIdx.x;
    const int mt   = blockIdx.y;
    const int tid  = threadIdx.x;
    const int lane = tid & 31;
    const int wid  = tid >> 5;
    const int wm   = wid & 3;   // 4 m-warps: rows wm*32..+32
    const int wn   = wid >> 2;  // 2 n-warps: cols wn*64..+64

    __shared__ __align__(16) unsigned char sm[2][2][128 * ROWB];  // [buf][A/B][row*80+col]

    float acc[2][8][4];
#pragma unroll
    for (int mb = 0; mb < 2; mb++)
#pragma unroll
        for (int nb = 0; nb < 8; nb++)
#pragma unroll
            for (int j = 0; j < 4; j++) acc[mb][nb][j] = 0.f;

    const uint4* gA = (const uint4*)g_Qb;
    const uint4* gB = (const uint4*)g_Db;

    // each thread owns 2 of the 512 16B-segments of each 128x32 tile
    const int s0 = tid, s1 = tid + 256;
    const int r0i = s0 >> 2, c0i = s0 & 3;
    const int r1i = s1 >> 2, c1i = s1 & 3;
    const uint4* pA0 = gA + (size_t)(mt * 128 + r0i) * (KD / 8) + c0i;
    const uint4* pA1 = gA + (size_t)(mt * 128 + r1i) * (KD / 8) + c1i;
    const uint4* pB0 = gB + (size_t)(nt * 128 + r0i) * (KD / 8) + c0i;
    const uint4* pB1 = gB + (size_t)(nt * 128 + r1i) * (KD / 8) + c1i;
    const unsigned off0 = r0i * ROWB + c0i * 16;
    const unsigned off1 = r1i * ROWB + c1i * 16;

    // prologue: load k-chunk 0
    uint4 ra0 = pA0[0], ra1 = pA1[0], rb0 = pB0[0], rb1 = pB1[0];
    *(uint4*)&sm[0][0][off0] = ra0;
    *(uint4*)&sm[0][0][off1] = ra1;
    *(uint4*)&sm[0][1][off0] = rb0;
    *(uint4*)&sm[0][1][off1] = rb1;
    __syncthreads();

    uint32_t smA[2], smB[2];
    smA[0] = (uint32_t)__cvta_generic_to_shared(&sm[0][0][0]);
    smB[0] = (uint32_t)__cvta_generic_to_shared(&sm[0][1][0]);
    smA[1] = (uint32_t)__cvta_generic_to_shared(&sm[1][0][0]);
    smB[1] = (uint32_t)__cvta_generic_to_shared(&sm[1][1][0]);

    for (int kc = 0; kc < 32; kc++) {
        const int cur = kc & 1;
        if (kc < 31) {  // prefetch next k-chunk into registers
            const int o = (kc + 1) * 4;
            ra0 = pA0[o]; ra1 = pA1[o]; rb0 = pB0[o]; rb1 = pB1[o];
        }
        const uint32_t aA = smA[cur] + (wm * 32 + (lane & 15)) * ROWB + ((lane >> 4) * 16);
        const uint32_t aB = smB[cur] + (wn * 64 + (lane & 15)) * ROWB + ((lane >> 4) * 16);
#pragma unroll
        for (int ks = 0; ks < 2; ks++) {
            uint32_t af[2][4];
            ldsm4(aA + ks * 32,             af[0][0], af[0][1], af[0][2], af[0][3]);
            ldsm4(aA + 16 * ROWB + ks * 32, af[1][0], af[1][1], af[1][2], af[1][3]);
            uint32_t bf[8][2];
#pragma unroll
            for (int nb2 = 0; nb2 < 4; nb2++) {
                uint32_t t0, t1, t2, t3;
                ldsm4(aB + nb2 * 16 * ROWB + ks * 32, t0, t1, t2, t3);
                bf[nb2 * 2][0]     = t0; bf[nb2 * 2][1]     = t2;
                bf[nb2 * 2 + 1][0] = t1; bf[nb2 * 2 + 1][1] = t3;
            }
#pragma unroll
            for (int mb = 0; mb < 2; mb++)
#pragma unroll
                for (int nb = 0; nb < 8; nb++)
                    mma16816(acc[mb][nb], af[mb], bf[nb]);
        }
        if (kc < 31) {
            const int nxt = 1 - cur;
            *(uint4*)&sm[nxt][0][off0] = ra0;
            *(uint4*)&sm[nxt][0][off1] = ra1;
            *(uint4*)&sm[nxt][1][off0] = rb0;
            *(uint4*)&sm[nxt][1][off1] = rb1;
        }
        __syncthreads();
    }

    // ---------------- epilogue: per-row max / sumexp over this 128-col tile ----------------
    float2* part = (float2*)&sm[0][0][0];  // part[row][wn]

#pragma unroll
    for (int mb = 0; mb < 2; mb++) {
#pragma unroll
        for (int rh = 0; rh < 2; rh++) {
            const int rloc = wm * 32 + mb * 16 + rh * 8 + (lane >> 2);
            const int grow = mt * 128 + rloc;
            float m = -1e30f;
#pragma unroll
            for (int nb = 0; nb < 8; nb++) {
                float v0 = acc[mb][nb][rh * 2 + 0] * INV_TEMP;
                float v1 = acc[mb][nb][rh * 2 + 1] * INV_TEMP;
                m = fmaxf(m, fmaxf(v0, v1));
            }
            float ssum = 0.f;
#pragma unroll
            for (int nb = 0; nb < 8; nb++) {
                float v0 = acc[mb][nb][rh * 2 + 0] * INV_TEMP;
                float v1 = acc[mb][nb][rh * 2 + 1] * INV_TEMP;
                ssum += __expf(v0 - m) + __expf(v1 - m);
                const int gcol = nt * 128 + wn * 64 + nb * 8 + (lane & 3) * 2;
                if (gcol     == 2 * grow) g_pos[grow] = v0;   // positive logit (unique writer)
                if (gcol + 1 == 2 * grow) g_pos[grow] = v1;
            }
            // butterfly combine among the 4 lanes holding this row (lane&3)
#pragma unroll
            for (int d_ = 1; d_ <= 2; d_ <<= 1) {
                float om = __shfl_xor_sync(0xffffffffu, m, d_);
                float os = __shfl_xor_sync(0xffffffffu, ssum, d_);
                float nm = fmaxf(m, om);
                ssum = ssum * __expf(m - nm) + os * __expf(om - nm);
                m = nm;
            }
            if ((lane & 3) == 0) part[rloc * 2 + wn] = make_float2(m, ssum);
        }
    }
    __syncthreads();
    if (tid < 128) {
        float2 p0 = part[tid * 2 + 0], p1 = part[tid * 2 + 1];
        float M = fmaxf(p0.x, p1.x);
        float S = p0.y * __expf(p0.x - M) + p1.y * __expf(p1.x - M);
        g_part[(size_t)(mt * 128 + tid) * NT_TILES + nt] = make_float2(M, S);
    }
}

// ---------------- kernel 3: combine 64 per-tile partials into per-row loss ----------------
__global__ __launch_bounds__(128) void row_lse_kernel() {
    const int r = blockIdx.x * 128 + threadIdx.x;
    const float2* p = &g_part[(size_t)r * NT_TILES];
    float M = -1e30f;
#pragma unroll 8
    for (int i = 0; i < NT_TILES; i++) M = fmaxf(M, p[i].x);
    float S = 0.f;
#pragma unroll 8
    for (int i = 0; i < NT_TILES; i++) S += p[i].y * __expf(p[i].x - M);
    g_rowloss[r] = (M + logf(S)) - g_pos[r];
}

// ---------------- kernel 4: deterministic tree reduction ----------------
__global__ __launch_bounds__(1024) void final_reduce(float* __restrict__ out) {
    __shared__ float s[1024];
    const int t = threadIdx.x;
    float v = g_rowloss[t] + g_rowloss[t + 1024] + g_rowloss[t + 2048] + g_rowloss[t + 3072];
    s[t] = v;
    __syncthreads();
    for (int d = 512; d > 0; d >>= 1) {
        if (t < d) s[t] += s[t + d];
        __syncthreads();
    }
    if (t == 0) out[0] = s[0] * (1.0f / (float)QB);
}

// ---------------- launch ----------------
extern "C" void kernel_launch(void* const* d_in, const int* in_sizes, int n_in,
                              void* d_out, int out_size) {
    const float* q  = (const float*)d_in[0];
    const float* dd = (const float*)d_in[1];
    float* out = (float*)d_out;

    const int total4 = (QB * KD + ND * KD) / 4;  // 3,145,728
    convert_kernel<<<total4 / 256, 256>>>(q, dd);
    gemm_lse_kernel<<<dim3(NT_TILES, QB / 128), 256>>>();
    row_lse_kernel<<<QB / 128, 128>>>();
    final_reduce<<<1, 1024>>>(out);
}